// round 17
// baseline (speedup 1.0000x reference)
#include <cuda_runtime.h>
#include <cuda_fp16.h>
#include <cstdint>
#include <cstddef>

#define N_NODES 12288
#define F 128
#define BM 128
#define BK 64
#define KSPLIT 12
#define KLEN (N_NODES / KSPLIT)     // 1024
#define KSTAGES (KLEN / BK)         // 16
#define TILES_M (N_NODES / BM)      // 96
#define GRID (TILES_M * KSPLIT)     // 1152
#define THREADS 512

#define A_BYTES (BM * 128)          // 16384 per A plane
#define ST_A2   (2 * A_BYTES)       // 32768: [sign][edge]
#define B_BYTES (128 * 128)         // 16384
#define STAGE_BYTES (ST_A2 + B_BYTES)   // 49152
#define SM_MAIN (2 * STAGE_BYTES)       // 98304
#define STG_NODE SM_MAIN
#define STG_EDGE (SM_MAIN + 32768)
#define SMEM_TOTAL (SM_MAIN + 65536)    // 163840

#define FH (F / 2)                      // 64 uints per row (fp16 pairs)
#define PLANE_H ((size_t)N_NODES * FH)
#define SLICE_H (2 * PLANE_H)

// tc_combine smem: 8 W tiles [g][pt][st] x 16KB + A tiles hi/lo x 2 stages
#define WT 16384
#define CB_W    0                       // 8 x 16KB = 131072
#define CB_AHI  131072                  // 2 stages x 16KB
#define CB_ALO  (131072 + 32768)        // 2 stages x 16KB
#define CB_SMEM (131072 + 65536)        // 196608

// Scratch
__device__ uint32_t g_S[(size_t)KSPLIT * 2 * N_NODES * FH];   // fp16 partials
__device__ uint4 g_fB[(size_t)(N_NODES / BK) * B_BYTES / 16];
__device__ float g_cpart[96 * F];
__device__ float g_b2[F];
__device__ unsigned char g_WB[8 * WT];   // swizzled hi/lo fp16 W tiles, 2 k-stages

// ---------------------------------------------------------------------------
// helpers
// ---------------------------------------------------------------------------
__device__ __forceinline__ uint32_t smem_u32(const void* p) {
    uint32_t a;
    asm("{ .reg .u64 t; cvta.to.shared.u64 t, %1; cvt.u32.u64 %0, t; }"
        : "=r"(a) : "l"(p));
    return a;
}

__device__ __forceinline__ uint32_t pack_h2(float lo, float hi) {
    __half2 h = __floats2half2_rn(lo, hi);
    return *(uint32_t*)&h;
}

__device__ __forceinline__ float sgnf(float v) {
    return (v > 0.f ? 1.f : 0.f) - (v < 0.f ? 1.f : 0.f);
}

#define SWX(off) ((off) ^ (((off) >> 3) & 0x70))
#define SSTG(t, q) ((uint32_t)(((t) * 64 + (q) * 16) ^ (((t) & 6) << 3)))

#define CP_ASYNC16(dst_u32, src) \
    asm volatile("cp.async.cg.shared.global [%0], [%1], 16;" \
                 :: "r"(dst_u32), "l"(src) : "memory")
#define CP_COMMIT() asm volatile("cp.async.commit_group;" ::: "memory")
#define CP_WAIT0()  asm volatile("cp.async.wait_group 0;" ::: "memory")
#define CP_WAIT1()  asm volatile("cp.async.wait_group 1;" ::: "memory")

#define LDS128F(v, addr) \
    asm volatile("ld.shared.v4.f32 {%0,%1,%2,%3}, [%4];" \
                 : "=f"((v).x), "=f"((v).y), "=f"((v).z), "=f"((v).w) : "r"(addr))

#define LDSM_X4(r0, r1, r2, r3, addr) \
    asm volatile("ldmatrix.sync.aligned.m8n8.x4.shared.b16 {%0,%1,%2,%3}, [%4];" \
                 : "=r"(r0), "=r"(r1), "=r"(r2), "=r"(r3) : "r"(addr))

__device__ __forceinline__ void mma_f16(float* d, const uint32_t* a,
                                        uint32_t b0, uint32_t b1) {
    asm volatile(
        "mma.sync.aligned.m16n8k16.row.col.f32.f16.f16.f32 "
        "{%0,%1,%2,%3}, {%4,%5,%6,%7}, {%8,%9}, {%0,%1,%2,%3};\n"
        : "+f"(d[0]), "+f"(d[1]), "+f"(d[2]), "+f"(d[3])
        : "r"(a[0]), "r"(a[1]), "r"(a[2]), "r"(a[3]), "r"(b0), "r"(b1));
}

// ---------------------------------------------------------------------------
// Prepass kernels
// ---------------------------------------------------------------------------
__global__ __launch_bounds__(128)
void colsum_kernel(const float* __restrict__ feats) {
    const int t = threadIdx.x;
    const int r0 = blockIdx.x * 128;
    float s = 0.f;
#pragma unroll 4
    for (int r = 0; r < 128; ++r)
        s += feats[(size_t)(r0 + r) * F + t];
    g_cpart[blockIdx.x * F + t] = s;
}

// b2 = nb + c@(Wtop+Wbot)/2 ; hi/lo fp16 B-format W tiles, 2 k-stages of 64,
// element (n, k) at tile[g][pt][k>>6] + SWX(n*128 + (k&63)*2).
__global__ __launch_bounds__(128)
void wtrans_kernel(const float* __restrict__ node_weight,
                   const float* __restrict__ node_bias,
                   const float* __restrict__ edge_weight) {
    __shared__ float cs[F];
    const int n = threadIdx.x;
    {
        float c = 0.f;
#pragma unroll 4
        for (int b = 0; b < 96; ++b)
            c += g_cpart[b * F + n];
        cs[n] = c;
    }
    __syncthreads();
    float b = node_bias[n];
#pragma unroll 4
    for (int k = 0; k < 128; ++k) {
        const float wt = node_weight[(size_t)k * F + n];
        const float wb = node_weight[(size_t)(k + 128) * F + n];
        const float wd = 0.5f * (wt - wb);
        b += cs[k] * 0.5f * (wt + wb);
        const float we = edge_weight[(size_t)k * F + n];
        const int st = k >> 6;
        const uint32_t off = SWX((uint32_t)(n * 128 + (k & 63) * 2));
        const __half dh = __float2half(wd);
        const __half eh = __float2half(we);
        // layout: [g*2 + pt] * 2 + st  (g: 0=Wd, 1=We; pt: 0=hi, 1=lo)
        *(__half*)(g_WB + (size_t)(0 * 2 + st) * WT + off) = dh;
        *(__half*)(g_WB + (size_t)(1 * 2 + st) * WT + off) =
            __float2half(wd - __half2float(dh));
        *(__half*)(g_WB + (size_t)(2 * 2 + st) * WT + off) = eh;
        *(__half*)(g_WB + (size_t)(3 * 2 + st) * WT + off) =
            __float2half(we - __half2float(eh));
    }
    g_b2[n] = b;
}

__global__ __launch_bounds__(256)
void prep_feats(const float* __restrict__ feats) {
    const int s = blockIdx.x;
    const int t = threadIdx.x;
    const int n = t >> 1;
    const int kh = (t & 1) * 32;
    const int jb = blockIdx.y * 8;
    uint32_t* out = (uint32_t*)g_fB + (size_t)s * (B_BYTES / 4);
    const float* src = feats + (size_t)(s * BK + kh) * F + n;
#pragma unroll
    for (int j = jb; j < jb + 8; j += 2) {
        const float v0 = src[(size_t)j * F];
        const float v1 = src[(size_t)(j + 1) * F];
        const uint32_t off = (uint32_t)(n * 128 + (kh + j) * 2);
        out[SWX(off) >> 2] = pack_h2(v0, v1);
    }
}

// ---------------------------------------------------------------------------
// Main kernel (frozen): split-K x12, BM=128, 16 warps.
// ---------------------------------------------------------------------------
__global__ __launch_bounds__(THREADS, 1)
void spmm2_f16(const float* __restrict__ node_adj,
               const float* __restrict__ edge_adj) {
    extern __shared__ char smem[];
    const uint32_t sb = smem_u32(smem);
    const int tid  = threadIdx.x;
    const int wid  = tid >> 5;
    const int lane = tid & 31;
    const int M0     = (blockIdx.x % TILES_M) * BM;
    const int kslice = blockIdx.x / TILES_M;
    const size_t K0  = (size_t)kslice * KLEN;

    const int cm = tid >> 2;
    const int kq = tid & 3;
    const float* nrow = node_adj + (size_t)(M0 + cm) * N_NODES + K0 + kq * 16;
    const float* erow = edge_adj + (size_t)(M0 + cm) * N_NODES + K0 + kq * 16;
    const uint32_t csts0 = SWX((uint32_t)(cm * 128 + kq * 32));
    const uint32_t csts1 = SWX((uint32_t)(cm * 128 + kq * 32 + 16));
    uint32_t stgNq[4], stgEq[4];
#pragma unroll
    for (int q = 0; q < 4; ++q) {
        stgNq[q] = sb + STG_NODE + SSTG(tid, q);
        stgEq[q] = sb + STG_EDGE + SSTG(tid, q);
    }

    const int wm = (wid & 7) * 16;
    const int wn = (wid >> 3) * 64;
    const uint32_t arow = wm + (lane & 15);
    const uint32_t abase = arow * 128 + (lane >> 4) * 16;
    const uint32_t axor = (arow & 7) << 4;
    uint32_t bbase[4], bxor[4];
#pragma unroll
    for (int np = 0; np < 4; ++np) {
        const uint32_t brow = wn + np * 16 + ((lane >> 4) << 3) + (lane & 7);
        bbase[np] = brow * 128 + ((lane >> 3) & 1) * 16;
        bxor[np]  = (brow & 7) << 4;
    }

    float acc[2][8][4];
#pragma unroll
    for (int p = 0; p < 2; ++p)
#pragma unroll
        for (int nt = 0; nt < 8; ++nt)
#pragma unroll
            for (int c = 0; c < 4; ++c) acc[p][nt][c] = 0.f;

    const char* fB = (const char*)g_fB + (size_t)(kslice * KSTAGES) * B_BYTES;

    auto stage_adj = [&](int s) {
        const size_t k0 = (size_t)s * BK;
#pragma unroll
        for (int q = 0; q < 4; ++q) {
            CP_ASYNC16(stgNq[q], nrow + k0 + q * 4);
            CP_ASYNC16(stgEq[q], erow + k0 + q * 4);
        }
    };
    auto stage_B = [&](int s, uint32_t buf_off) {
        const uint32_t dst = sb + buf_off + ST_A2 + tid * 32;
        const char* src = fB + (size_t)s * B_BYTES + tid * 32;
        CP_ASYNC16(dst, src);
        CP_ASYNC16(dst + 16, src + 16);
    };
    auto convert = [&](uint32_t dbuf_off) {
        char* bp = smem + dbuf_off;
        {
            float4 n0, n1, n2, n3;
            LDS128F(n0, stgNq[0]); LDS128F(n1, stgNq[1]);
            LDS128F(n2, stgNq[2]); LDS128F(n3, stgNq[3]);
            uint4 S0, S1;
            S0 = make_uint4(pack_h2(sgnf(n0.x), sgnf(n0.y)), pack_h2(sgnf(n0.z), sgnf(n0.w)),
                            pack_h2(sgnf(n1.x), sgnf(n1.y)), pack_h2(sgnf(n1.z), sgnf(n1.w)));
            S1 = make_uint4(pack_h2(sgnf(n2.x), sgnf(n2.y)), pack_h2(sgnf(n2.z), sgnf(n2.w)),
                            pack_h2(sgnf(n3.x), sgnf(n3.y)), pack_h2(sgnf(n3.z), sgnf(n3.w)));
            *(uint4*)(bp + 0 * A_BYTES + csts0) = S0;
            *(uint4*)(bp + 0 * A_BYTES + csts1) = S1;
        }
        {
            float4 e0, e1, e2, e3;
            LDS128F(e0, stgEq[0]); LDS128F(e1, stgEq[1]);
            LDS128F(e2, stgEq[2]); LDS128F(e3, stgEq[3]);
            uint4 E0, E1;
            E0 = make_uint4(pack_h2(e0.x, e0.y), pack_h2(e0.z, e0.w),
                            pack_h2(e1.x, e1.y), pack_h2(e1.z, e1.w));
            E1 = make_uint4(pack_h2(e2.x, e2.y), pack_h2(e2.z, e2.w),
                            pack_h2(e3.x, e3.y), pack_h2(e3.z, e3.w));
            *(uint4*)(bp + 1 * A_BYTES + csts0) = E0;
            *(uint4*)(bp + 1 * A_BYTES + csts1) = E1;
        }
    };

    stage_B(0, 0);
    stage_adj(0);
    CP_COMMIT();
    CP_WAIT0();
    convert(0);
    stage_adj(1);
    CP_COMMIT();
    __syncthreads();

#pragma unroll 1
    for (int s = 0; s < KSTAGES; ++s) {
        const uint32_t cur = (uint32_t)(s & 1) * STAGE_BYTES;
        const uint32_t nxt = (uint32_t)((s + 1) & 1) * STAGE_BYTES;

        if (s + 1 < KSTAGES) {
            stage_B(s + 1, nxt);
            CP_COMMIT();
        }

        const uint32_t sbA = sb + cur;
        const uint32_t sbB = sb + cur + ST_A2;
#pragma unroll
        for (int ks = 0; ks < 4; ++ks) {
            uint32_t b[4][4];
#pragma unroll
            for (int np = 0; np < 4; ++np)
                LDSM_X4(b[np][0], b[np][1], b[np][2], b[np][3],
                        sbB + ((bbase[np] + ks * 32) ^ bxor[np]));
#pragma unroll
            for (int p = 0; p < 2; ++p) {
                uint32_t a[4];
                LDSM_X4(a[0], a[1], a[2], a[3],
                        sbA + p * A_BYTES + ((abase + ks * 32) ^ axor));
#pragma unroll
                for (int np = 0; np < 4; ++np) {
                    mma_f16(acc[p][np * 2],     a, b[np][0], b[np][1]);
                    mma_f16(acc[p][np * 2 + 1], a, b[np][2], b[np][3]);
                }
            }
        }

        if (s + 1 < KSTAGES) {
            CP_WAIT1();
            convert(nxt);
            if (s + 2 < KSTAGES) {
                stage_adj(s + 2);
                CP_COMMIT();
                CP_WAIT1();
            } else {
                CP_WAIT0();
            }
            __syncthreads();
        }
    }

    const int er0 = wm + (lane >> 2);
    const int ec0 = wn + (lane & 3) * 2;
#pragma unroll
    for (int p = 0; p < 2; ++p) {
        uint32_t* base = g_S + (size_t)kslice * SLICE_H + (size_t)p * PLANE_H
                       + (size_t)(M0 + er0) * FH + (ec0 >> 1);
#pragma unroll
        for (int nt = 0; nt < 8; ++nt) {
            base[nt * 4]          = pack_h2(acc[p][nt][0], acc[p][nt][1]);
            base[8 * FH + nt * 4] = pack_h2(acc[p][nt][2], acc[p][nt][3]);
        }
    }
}

// ---------------------------------------------------------------------------
// Tensor-core combine: grid 96 x 512 threads, 128 rows/CTA, K=128 as 2 stages
// of 64 in the main kernel's proven tile format.
// out = relu(Ssign@Wd + b2) + Sedge@We + eb
// ---------------------------------------------------------------------------
__global__ __launch_bounds__(512, 1)
void tc_combine(const float* __restrict__ edge_bias,
                float* __restrict__ out) {
    extern __shared__ char smem[];
    const uint32_t sb = smem_u32(smem);
    const int tid = threadIdx.x;
    const int wid = tid >> 5;
    const int lane = tid & 31;
    const int R0 = blockIdx.x * 128;

    // W tiles: 131072 bytes, 256B per thread
    {
        const unsigned char* src = g_WB + tid * 256;
        const uint32_t dst = sb + CB_W + tid * 256;
#pragma unroll
        for (int q = 0; q < 16; ++q) CP_ASYNC16(dst + q * 16, src + q * 16);
        CP_COMMIT();
    }

    // mma mapping (identical to main): 8m x 2n warps
    const int wm = (wid & 7) * 16;
    const int wn = (wid >> 3) * 64;
    const uint32_t arow = wm + (lane & 15);
    const uint32_t abase = arow * 128 + (lane >> 4) * 16;
    const uint32_t axor = (arow & 7) << 4;
    uint32_t bbase[4], bxor[4];
#pragma unroll
    for (int np = 0; np < 4; ++np) {
        const uint32_t brow = wn + np * 16 + ((lane >> 4) << 3) + (lane & 7);
        bbase[np] = brow * 128 + ((lane >> 3) & 1) * 16;
        bxor[np]  = (brow & 7) << 4;
    }

    // A-fill: row ar = tid>>2, cg = tid&3 selects k in [cg*32, cg*32+32);
    // stage st = cg>>1; local k base = (cg&1)*64 bytes... (k&63)*2 bytes.
    const int ar = tid >> 2;
    const int cg = tid & 3;
    const int ast = cg >> 1;                 // k-stage of this thread's chunk
    const uint32_t albase = (uint32_t)(ar * 128 + (cg & 1) * 64);
    auto a_fill = [&](int p) {
        const uint32_t* src = g_S + (size_t)p * PLANE_H + (size_t)(R0 + ar) * FH + cg * 16;
#pragma unroll
        for (int h = 0; h < 2; ++h) {        // h: 16 k-values (8 uints) each
            float s[16];
#pragma unroll
            for (int i = 0; i < 16; ++i) s[i] = 0.f;
#pragma unroll
            for (int sl = 0; sl < KSPLIT; ++sl) {
                const uint4 v0 = *(const uint4*)(src + (size_t)sl * SLICE_H + h * 8);
                const uint4 v1 = *(const uint4*)(src + (size_t)sl * SLICE_H + h * 8 + 4);
                const uint32_t vv[8] = {v0.x, v0.y, v0.z, v0.w, v1.x, v1.y, v1.z, v1.w};
#pragma unroll
                for (int i = 0; i < 8; ++i) {
                    const float2 f = __half22float2(*(const __half2*)&vv[i]);
                    s[i * 2]     += f.x;
                    s[i * 2 + 1] += f.y;
                }
            }
            uint32_t hi[8], lo[8];
#pragma unroll
            for (int i = 0; i < 8; ++i) {
                hi[i] = pack_h2(s[i * 2], s[i * 2 + 1]);
                const float2 f = __half22float2(*(const __half2*)&hi[i]);
                lo[i] = pack_h2(s[i * 2] - f.x, s[i * 2 + 1] - f.y);
            }
            const uint32_t off0 = SWX(albase + h * 32);
            const uint32_t off1 = SWX(albase + h * 32 + 16);
            char* dhi = smem + CB_AHI + ast * WT;
            char* dlo = smem + CB_ALO + ast * WT;
            *(uint4*)(dhi + off0) = make_uint4(hi[0], hi[1], hi[2], hi[3]);
            *(uint4*)(dhi + off1) = make_uint4(hi[4], hi[5], hi[6], hi[7]);
            *(uint4*)(dlo + off0) = make_uint4(lo[0], lo[1], lo[2], lo[3]);
            *(uint4*)(dlo + off1) = make_uint4(lo[4], lo[5], lo[6], lo[7]);
        }
    };

    // gemm over 2 k-stages x 4 k-steps; g selects W tile group (0=Wd, 1=We)
    auto gemm = [&](int g, float (*acc)[4]) {
#pragma unroll
        for (int st = 0; st < 2; ++st) {
            const uint32_t aHI = sb + CB_AHI + st * WT;
            const uint32_t aLO = sb + CB_ALO + st * WT;
            const uint32_t bHI = sb + CB_W + (uint32_t)((g * 2 + 0) * 2 + st) * WT;
            const uint32_t bLO = sb + CB_W + (uint32_t)((g * 2 + 1) * 2 + st) * WT;
#pragma unroll
            for (int ks = 0; ks < 4; ++ks) {
                const uint32_t ko = (uint32_t)ks * 32;
                uint32_t ah[4], al[4];
                LDSM_X4(ah[0], ah[1], ah[2], ah[3], aHI + ((abase + ko) ^ axor));
                LDSM_X4(al[0], al[1], al[2], al[3], aLO + ((abase + ko) ^ axor));
#pragma unroll
                for (int np = 0; np < 4; ++np) {
                    uint32_t bh[4], bl[4];
                    LDSM_X4(bh[0], bh[1], bh[2], bh[3],
                            bHI + ((bbase[np] + ko) ^ bxor[np]));
                    LDSM_X4(bl[0], bl[1], bl[2], bl[3],
                            bLO + ((bbase[np] + ko) ^ bxor[np]));
                    mma_f16(acc[np * 2],     ah, bh[0], bh[1]);
                    mma_f16(acc[np * 2 + 1], ah, bh[2], bh[3]);
                    mma_f16(acc[np * 2],     ah, bl[0], bl[1]);
                    mma_f16(acc[np * 2 + 1], ah, bl[2], bl[3]);
                    mma_f16(acc[np * 2],     al, bh[0], bh[1]);
                    mma_f16(acc[np * 2 + 1], al, bh[2], bh[3]);
                }
            }
        }
    };

    float accN[8][4], accE[8][4];
#pragma unroll
    for (int nt = 0; nt < 8; ++nt)
#pragma unroll
        for (int c = 0; c < 4; ++c) { accN[nt][c] = 0.f; accE[nt][c] = 0.f; }

    a_fill(0);                    // sign plane sums -> A tiles
    CP_WAIT0();                   // W tiles landed
    __syncthreads();
    gemm(0, accN);
    __syncthreads();
    a_fill(1);                    // edge plane sums -> A tiles
    __syncthreads();
    gemm(1, accE);

    // epilogue
    const int er = R0 + wm + (lane >> 2);
    const int c0 = wn + (lane & 3) * 2;
#pragma unroll
    for (int nt = 0; nt < 8; ++nt) {
        const int c = c0 + nt * 8;
        const float2 b2 = *(const float2*)(g_b2 + c);
        const float2 eb = *(const float2*)(edge_bias + c);
        float2 o0, o1;
        o0.x = fmaxf(accN[nt][0] + b2.x, 0.f) + accE[nt][0] + eb.x;
        o0.y = fmaxf(accN[nt][1] + b2.y, 0.f) + accE[nt][1] + eb.y;
        o1.x = fmaxf(accN[nt][2] + b2.x, 0.f) + accE[nt][2] + eb.x;
        o1.y = fmaxf(accN[nt][3] + b2.y, 0.f) + accE[nt][3] + eb.y;
        *(float2*)(out + (size_t)er * F + c)       = o0;
        *(float2*)(out + (size_t)(er + 8) * F + c) = o1;
    }
}

extern "C" void kernel_launch(void* const* d_in, const int* in_sizes, int n_in,
                              void* d_out, int out_size) {
    const float* feats       = (const float*)d_in[0];
    const float* node_adj    = (const float*)d_in[1];
    const float* edge_adj    = (const float*)d_in[2];
    const float* node_weight = (const float*)d_in[3];
    const float* node_bias   = (const float*)d_in[4];
    const float* edge_weight = (const float*)d_in[5];
    const float* edge_bias   = (const float*)d_in[6];
    float* out = (float*)d_out;

    cudaFuncSetAttribute(spmm2_f16, cudaFuncAttributeMaxDynamicSharedMemorySize, SMEM_TOTAL);
    cudaFuncSetAttribute(tc_combine, cudaFuncAttributeMaxDynamicSharedMemorySize, CB_SMEM);

    colsum_kernel<<<96, 128>>>(feats);
    wtrans_kernel<<<1, 128>>>(node_weight, node_bias, edge_weight);
    prep_feats<<<dim3(N_NODES / BK, 4), 256>>>(feats);
    spmm2_f16<<<GRID, THREADS, SMEM_TOTAL>>>(node_adj, edge_adj);
    tc_combine<<<TILES_M, 512, CB_SMEM>>>(edge_bias, out);
}